// round 12
// baseline (speedup 1.0000x reference)
#include <cuda_runtime.h>
#include <math.h>

#define NSAMP  24000
#define CH     4             // samples per lane
#define SPW    128           // samples per warp (32 * 4)
#define CUTOFF 0.1f
#define OMC    0.9f          // 1 - CUTOFF
#define A4     0.6561f       // 0.9^4
#define TSTEP  (1.0f / 23999.0f)
#define INV2PI 0.15915494309f
#define SMEM_BYTES (2u * NSAMP * sizeof(float))

// Global scratch (device global: no allocation)
__device__ float g_trans[NSAMP];

__device__ __forceinline__ float tanh_fast(float x) {
    // exact identity tanh(x) = 1 - 2/(e^{2x}+1); saturates correctly at +-inf
    float e = __expf(2.0f * x);
    return 1.0f - __fdividef(2.0f, e + 1.0f);
}

// sincos for args up to ~400 rad: 2-term Cody-Waite reduction + MUFU sin/cos.
__device__ __forceinline__ void sincos_cw(float x, float* s, float* c) {
    float k = rintf(x * INV2PI);
    float r = fmaf(k, -6.28125f, x);          // 2pi hi (exact in fp32)
    r = fmaf(k, -1.9353072e-3f, r);           // 2pi lo
    *s = __sinf(r);
    *c = __cosf(r);
}

__device__ __forceinline__ void cluster_sync() {
    asm volatile("barrier.cluster.arrive.aligned;" ::: "memory");   // release
    asm volatile("barrier.cluster.wait.aligned;"   ::: "memory");   // acquire
}

__global__ __launch_bounds__(1024, 1)
void drum_synth_cluster(const float* __restrict__ p,
                        const float* __restrict__ noise_t,
                        const float* __restrict__ noise_n,
                        float* __restrict__ out)
{
    extern __shared__ float sm[];      // str[24000] trans copy, sre[24000] resonator
    float* str = sm;
    float* sre = sm + NSAMP;

    const int tid  = threadIdx.x;
    const int lane = tid & 31;
    const int nthr = blockDim.x;
    const int w    = blockIdx.x * (nthr >> 5) + (tid >> 5);   // global warp 0..255

    const int  s0  = w * SPW + lane * CH;
    const bool act = (s0 + CH <= NSAMP);
    const int  v0  = s0 >> 2;                       // float4 index (1 per lane)
    const float4* ntv = (const float4*)noise_t;

    // ---- earliest possible: prime noise_n into L2/regs (cold DRAM) ----
    float4 nn0 = make_float4(0.f, 0.f, 0.f, 0.f);
    if (act) nn0 = ((const float4*)noise_n)[v0];

    const float decay_t  = p[1];
    const float freq_t   = p[2];
    const float sat      = p[3];
    const float gain_t   = p[4];
    const float freq_r   = p[5];
    const float feedback = p[6];
    const float gain_r   = p[7];
    const float attack_n = p[8];
    const float decay_n  = p[9];
    const float gain_n   = p[10];

    // ======== Phase A1: halo — redundantly reduce previous warp's 128 samples ====
    float ha = 1.0f, hb = 0.0f;
    {
        const int hs0 = s0 - SPW;
        if (hs0 >= 0 && hs0 + CH <= NSAMP) {
            float4 x0 = ntv[hs0 >> 2];
            float y;
            y = CUTOFF * x0.x;
            y = fmaf(OMC, y, CUTOFF * x0.y);
            y = fmaf(OMC, y, CUTOFF * x0.z);
            y = fmaf(OMC, y, CUTOFF * x0.w);
            hb = y; ha = A4;
        }
    }
    #pragma unroll
    for (int off = 1; off < 32; off <<= 1) {
        float au = __shfl_up_sync(0xffffffffu, ha, off);
        float bu = __shfl_up_sync(0xffffffffu, hb, off);
        if (lane >= off) { hb = fmaf(ha, bu, hb); ha *= au; }
    }
    const float y_warp = __shfl_sync(0xffffffffu, hb, 31);   // filter state at warp start

    // ======== Phase A2: main chunk partials from y=0 (register-resident) ========
    float bk[CH];
    float ma = 1.0f, mb = 0.0f;
    if (act) {
        float4 x0 = ntv[v0];
        float xs[CH] = {x0.x, x0.y, x0.z, x0.w};
        float y = 0.0f;
        #pragma unroll
        for (int s = 0; s < CH; ++s) { y = fmaf(OMC, y, CUTOFF * xs[s]); bk[s] = y; }
        mb = y; ma = A4;
    }
    #pragma unroll
    for (int off = 1; off < 32; off <<= 1) {
        float au = __shfl_up_sync(0xffffffffu, ma, off);
        float bu = __shfl_up_sync(0xffffffffu, mb, off);
        if (lane >= off) { mb = fmaf(ma, bu, mb); ma *= au; }
    }
    float a_ie = __shfl_up_sync(0xffffffffu, ma, 1);
    float b_ie = __shfl_up_sync(0xffffffffu, mb, 1);
    if (lane == 0) { a_ie = 1.0f; b_ie = 0.0f; }
    const float y_in = fmaf(a_ie, y_warp, b_ie);

    // ======== Phase A3: transient via spiral/geometric recurrences ========
    float tr[CH];
    if (act) {
        const float t0 = (float)s0 * TSTEP;
        const float wf = 6.2831853f * freq_t;
        float sn, cs;
        sincos_cw(wf * t0, &sn, &cs);               // Cody-Waite + MUFU
        const float sd = __sinf(wf * TSTEP);        // tiny-arg step rotation
        const float cd = __cosf(wf * TSTEP);
        const float m1 = __expf(-decay_t * TSTEP);
        const float m2 = __expf(-20.0f * decay_t * TSTEP);
        const float cdm = cd * m1, sdm = sd * m1;   // rotation x decay fused
        const float K  = gain_t * sat;
        const float e1 = __expf(-decay_t * t0);
        float u = sn * e1 * K;                       // tanh argument
        float v = cs * e1 * K;
        float e2g = __expf(-20.0f * decay_t * t0) * (gain_t * 0.5f);
        float q   = OMC * y_in * e2g;                // 0.9^{s+1} * y_in * e2g_s
        const float cq = OMC * m2;
        #pragma unroll
        for (int s = 0; s < CH; ++s) {
            float sq = tanh_fast(u);                 // saturated sine
            tr[s] = sq + fmaf(bk[s], e2g, q);        // + filtered-noise component
            float u2 = fmaf(u, cdm,  v * sdm);       // spiral step
            float v2 = fmaf(v, cdm, -u * sdm);
            u = u2; v = v2;
            e2g *= m2; q *= cq;
        }
        ((float4*)g_trans)[v0] = make_float4(tr[0], tr[1], tr[2], tr[3]);
    }

    // ---- phase-C envelope setup: overlaps sync + staging ----
    const float t0c = (float)s0 * TSTEP;
    float eA = __expf(-attack_n * t0c);
    float eD = __expf(-decay_n  * t0c);
    const float a1 = __expf(-attack_n * TSTEP);
    const float d1 = __expf(-decay_n  * TSTEP);

    // cluster barrier: arrive=release orders g_trans stores; wait=acquire.
    cluster_sync();

    // ======== Phase B: resonator, REDUNDANT per CTA, chains run from smem ========
    // Stage g_trans -> local smem (coalesced float4 burst, high MLP)
    {
        const float4* tv = (const float4*)g_trans;
        float4*       sv = (float4*)str;
        for (int i4 = tid; i4 < NSAMP / 4; i4 += nthr) sv[i4] = tv[i4];
    }

    const float D  = 48000.0f / freq_r;
    const int   Di = (int)D;
    const bool fastp = (D >= 1.0f) && ((float)Di == D) && (Di < NSAMP);

    if (fastp) {
        __syncthreads();
        // Integer delay: frac == 0 exactly -> Di independent chains, LDS-fed.
        for (int r = tid; r < Di; r += nthr) {
            float yv = str[r];            // i < D => valid==0 => out = transient
            sre[r] = yv;
            #pragma unroll 5
            for (int i = r + Di; i < NSAMP; i += Di) {
                yv = fmaf(feedback, yv, str[i]);
                sre[i] = yv;
            }
        }
        __syncthreads();
    } else {
        // Generic fractional delay: wave-synchronous over zeroed smem res.
        for (int i = tid; i < NSAMP; i += nthr) sre[i] = 0.0f;
        __syncthreads();
        if (tid == 0) sre[0] = str[0];
        int cD = (int)ceilf(D);
        int W  = min(max(cD - 1, 1), nthr);
        __syncthreads();
        for (int b0 = 1; b0 < NSAMP; b0 += W) {
            const int i = b0 + tid;
            if (tid < W && i < NSAMP) {
                float delayed = (float)i - D;
                float valid   = (delayed >= 0.0f) ? 1.0f : 0.0f;
                int fl = min(max((int)floorf(delayed), 0), NSAMP - 1);
                int ce = min(fl + 1, NSAMP - 1);
                float frac = delayed - (float)fl;   // after clamp, as in reference
                float interp = (1.0f - frac) * sre[fl] + frac * sre[ce];
                sre[i] = str[i] + feedback * interp * valid;
            }
            __syncthreads();
        }
    }

    // ======== Phase C: noise envelope + final sum (tr in regs, res in smem) ====
    if (act) {
        float4 rs0 = ((const float4*)sre)[v0];
        const float nnf[CH] = {nn0.x, nn0.y, nn0.z, nn0.w};
        const float rsf[CH] = {rs0.x, rs0.y, rs0.z, rs0.w};
        float o[CH];
        float eAk = eA, eDk = eD;
        #pragma unroll
        for (int s = 0; s < CH; ++s) {
            float env = (1.0f - eAk) * eDk;
            o[s] = fmaf(nnf[s] * gain_n, env, fmaf(rsf[s], gain_r, tr[s]));
            eAk *= a1; eDk *= d1;
        }
        ((float4*)out)[v0] = make_float4(o[0], o[1], o[2], o[3]);
    }
}

extern "C" void kernel_launch(void* const* d_in, const int* in_sizes, int n_in,
                              void* d_out, int out_size)
{
    const float* params  = (const float*)d_in[0];
    const float* noise_t = (const float*)d_in[1];
    const float* noise_n = (const float*)d_in[2];
    float* out = (float*)d_out;

    cudaFuncSetAttribute(drum_synth_cluster,
                         cudaFuncAttributeMaxDynamicSharedMemorySize,
                         (int)SMEM_BYTES);
    cudaFuncSetAttribute(drum_synth_cluster,
                         cudaFuncAttributeNonPortableClusterSizeAllowed, 1);

    // Preferred: 16-CTA cluster, 512 threads each (same 256-warp lane map).
    cudaLaunchConfig_t cfg = {};
    cfg.gridDim         = dim3(16, 1, 1);
    cfg.blockDim        = dim3(512, 1, 1);
    cfg.dynamicSmemBytes = SMEM_BYTES;
    cfg.stream          = 0;

    int maxc = 0;
    if (cudaOccupancyMaxPotentialClusterSize(&maxc, drum_synth_cluster, &cfg)
        != cudaSuccess) maxc = 8;

    cudaLaunchAttribute attrs[1];
    attrs[0].id = cudaLaunchAttributeClusterDimension;

    if (maxc >= 16) {
        attrs[0].val.clusterDim = {16, 1, 1};
        cfg.attrs = attrs; cfg.numAttrs = 1;
        cudaLaunchKernelEx(&cfg, drum_synth_cluster, params, noise_t, noise_n, out);
    } else {
        // Fallback: proven 8-CTA x 1024-thread configuration (identical lane map).
        cfg.gridDim  = dim3(8, 1, 1);
        cfg.blockDim = dim3(1024, 1, 1);
        attrs[0].val.clusterDim = {8, 1, 1};
        cfg.attrs = attrs; cfg.numAttrs = 1;
        cudaLaunchKernelEx(&cfg, drum_synth_cluster, params, noise_t, noise_n, out);
    }
}

// round 13
// speedup vs baseline: 1.0208x; 1.0208x over previous
#include <cuda_runtime.h>
#include <math.h>

#define NSAMP  24000
#define CH     4             // samples per lane
#define SPW    128           // samples per warp (32 * 4)
#define CUTOFF 0.1f
#define OMC    0.9f          // 1 - CUTOFF
#define A4     0.6561f       // 0.9^4
#define LN_A4  (-0.42144206f) // ln(0.9^4)
#define TSTEP  (1.0f / 23999.0f)
#define INV2PI 0.15915494309f
#define SMEM_BYTES (2u * NSAMP * sizeof(float))

// Global scratch (device global: no allocation)
__device__ float g_trans[NSAMP];

__device__ __forceinline__ float tanh_fast(float x) {
    // exact identity tanh(x) = 1 - 2/(e^{2x}+1); saturates correctly at +-inf
    float e = __expf(2.0f * x);
    return 1.0f - __fdividef(2.0f, e + 1.0f);
}

// sincos for args up to ~400 rad: 2-term Cody-Waite reduction + MUFU sin/cos.
__device__ __forceinline__ void sincos_cw(float x, float* s, float* c) {
    float k = rintf(x * INV2PI);
    float r = fmaf(k, -6.28125f, x);          // 2pi hi (exact in fp32)
    r = fmaf(k, -1.9353072e-3f, r);           // 2pi lo
    *s = __sinf(r);
    *c = __cosf(r);
}

// Constant-coefficient inclusive scan: b_L = sum_{j<=L} A4^(L-j) b_j.
// One shfl + one fma per level (coefficient is lane-invariant).
__device__ __forceinline__ float scan_const_a4(float b, int lane) {
    const float P[5] = {0.6561f, 0.43046721f, 0.18530202f,
                        0.034336838f, 0.0011790185f};   // A4^{1,2,4,8,16}
    #pragma unroll
    for (int k = 0; k < 5; ++k) {
        int off = 1 << k;
        float bu = __shfl_up_sync(0xffffffffu, b, off);
        if (lane >= off) b = fmaf(P[k], bu, b);
    }
    return b;
}

__device__ __forceinline__ void cluster_sync() {
    asm volatile("barrier.cluster.arrive.aligned;" ::: "memory");   // release
    asm volatile("barrier.cluster.wait.aligned;"   ::: "memory");   // acquire
}

__global__ __launch_bounds__(1024, 1)
void drum_synth_cluster(const float* __restrict__ p,
                        const float* __restrict__ noise_t,
                        const float* __restrict__ noise_n,
                        float* __restrict__ out)
{
    extern __shared__ float sm[];      // str[24000] trans copy, sre[24000] resonator
    float* str = sm;
    float* sre = sm + NSAMP;

    const int tid  = threadIdx.x;
    const int lane = tid & 31;
    const int nthr = blockDim.x;
    const int w    = blockIdx.x * (nthr >> 5) + (tid >> 5);   // global warp 0..255

    const int  s0  = w * SPW + lane * CH;
    const bool act = (s0 + CH <= NSAMP);
    const int  v0  = s0 >> 2;                       // float4 index (1 per lane)
    const float4* ntv = (const float4*)noise_t;

    // ---- earliest possible: prime noise_n into L2/regs (cold DRAM) ----
    float4 nn0 = make_float4(0.f, 0.f, 0.f, 0.f);
    if (act) nn0 = ((const float4*)noise_n)[v0];

    const float decay_t  = p[1];
    const float freq_t   = p[2];
    const float sat      = p[3];
    const float gain_t   = p[4];
    const float freq_r   = p[5];
    const float feedback = p[6];
    const float gain_r   = p[7];
    const float attack_n = p[8];
    const float decay_n  = p[9];
    const float gain_n   = p[10];

    // ======== Phase A1: halo — redundantly reduce previous warp's 128 samples ====
    float hb = 0.0f;
    {
        const int hs0 = s0 - SPW;
        if (hs0 >= 0 && hs0 + CH <= NSAMP) {
            float4 x0 = ntv[hs0 >> 2];
            float y;
            y = CUTOFF * x0.x;
            y = fmaf(OMC, y, CUTOFF * x0.y);
            y = fmaf(OMC, y, CUTOFF * x0.z);
            y = fmaf(OMC, y, CUTOFF * x0.w);
            hb = y;
        }
    }
    hb = scan_const_a4(hb, lane);
    const float y_warp = __shfl_sync(0xffffffffu, hb, 31);   // filter state at warp start

    // ======== Phase A2: main chunk partials from y=0 (register-resident) ========
    float bk[CH];
    float mb = 0.0f;
    if (act) {
        float4 x0 = ntv[v0];
        float xs[CH] = {x0.x, x0.y, x0.z, x0.w};
        float y = 0.0f;
        #pragma unroll
        for (int s = 0; s < CH; ++s) { y = fmaf(OMC, y, CUTOFF * xs[s]); bk[s] = y; }
        mb = y;
    }
    mb = scan_const_a4(mb, lane);
    float b_ie = __shfl_up_sync(0xffffffffu, mb, 1);
    if (lane == 0) b_ie = 0.0f;
    const float a_ie = __expf((float)lane * LN_A4);          // A4^lane (exp(0)=1)
    const float y_in = fmaf(a_ie, y_warp, b_ie);

    // ======== Phase A3: transient via spiral/geometric recurrences ========
    float tr[CH];
    if (act) {
        const float t0 = (float)s0 * TSTEP;
        const float wf = 6.2831853f * freq_t;
        float sn, cs;
        sincos_cw(wf * t0, &sn, &cs);               // Cody-Waite + MUFU
        const float sd = __sinf(wf * TSTEP);        // tiny-arg step rotation
        const float cd = __cosf(wf * TSTEP);
        const float m1 = __expf(-decay_t * TSTEP);
        const float m2 = __expf(-20.0f * decay_t * TSTEP);
        const float cdm = cd * m1, sdm = sd * m1;   // rotation x decay fused
        const float K  = gain_t * sat;
        const float e1 = __expf(-decay_t * t0);
        float u = sn * e1 * K;                       // tanh argument
        float v = cs * e1 * K;
        float e2g = __expf(-20.0f * decay_t * t0) * (gain_t * 0.5f);
        float q   = OMC * y_in * e2g;                // 0.9^{s+1} * y_in * e2g_s
        const float cq = OMC * m2;
        #pragma unroll
        for (int s = 0; s < CH; ++s) {
            float sq = tanh_fast(u);                 // saturated sine
            tr[s] = sq + fmaf(bk[s], e2g, q);        // + filtered-noise component
            float u2 = fmaf(u, cdm,  v * sdm);       // spiral step
            float v2 = fmaf(v, cdm, -u * sdm);
            u = u2; v = v2;
            e2g *= m2; q *= cq;
        }
        ((float4*)g_trans)[v0] = make_float4(tr[0], tr[1], tr[2], tr[3]);
    }

    // ---- phase-C envelope setup: overlaps sync + staging ----
    const float t0c = (float)s0 * TSTEP;
    float eA = __expf(-attack_n * t0c);
    float eD = __expf(-decay_n  * t0c);
    const float a1 = __expf(-attack_n * TSTEP);
    const float d1 = __expf(-decay_n  * TSTEP);

    // cluster barrier: arrive=release orders g_trans stores; wait=acquire.
    cluster_sync();

    // ======== Phase B: resonator, REDUNDANT per CTA, chains run from smem ========
    // Stage g_trans -> local smem (coalesced float4 burst, high MLP)
    {
        const float4* tv = (const float4*)g_trans;
        float4*       sv = (float4*)str;
        for (int i4 = tid; i4 < NSAMP / 4; i4 += nthr) sv[i4] = tv[i4];
    }

    const float D  = 48000.0f / freq_r;
    const int   Di = (int)D;
    const bool fastp = (D >= 1.0f) && ((float)Di == D) && (Di < NSAMP);

    if (fastp) {
        __syncthreads();
        // Integer delay: frac == 0 exactly -> Di independent chains, LDS-fed.
        for (int r = tid; r < Di; r += nthr) {
            float yv = str[r];            // i < D => valid==0 => out = transient
            sre[r] = yv;
            #pragma unroll 5
            for (int i = r + Di; i < NSAMP; i += Di) {
                yv = fmaf(feedback, yv, str[i]);
                sre[i] = yv;
            }
        }
        __syncthreads();
    } else {
        // Generic fractional delay: wave-synchronous over zeroed smem res.
        for (int i = tid; i < NSAMP; i += nthr) sre[i] = 0.0f;
        __syncthreads();
        if (tid == 0) sre[0] = str[0];
        int cD = (int)ceilf(D);
        int W  = min(max(cD - 1, 1), nthr);
        __syncthreads();
        for (int b0 = 1; b0 < NSAMP; b0 += W) {
            const int i = b0 + tid;
            if (tid < W && i < NSAMP) {
                float delayed = (float)i - D;
                float valid   = (delayed >= 0.0f) ? 1.0f : 0.0f;
                int fl = min(max((int)floorf(delayed), 0), NSAMP - 1);
                int ce = min(fl + 1, NSAMP - 1);
                float frac = delayed - (float)fl;   // after clamp, as in reference
                float interp = (1.0f - frac) * sre[fl] + frac * sre[ce];
                sre[i] = str[i] + feedback * interp * valid;
            }
            __syncthreads();
        }
    }

    // ======== Phase C: noise envelope + final sum (tr in regs, res in smem) ====
    if (act) {
        float4 rs0 = ((const float4*)sre)[v0];
        const float nnf[CH] = {nn0.x, nn0.y, nn0.z, nn0.w};
        const float rsf[CH] = {rs0.x, rs0.y, rs0.z, rs0.w};
        float o[CH];
        float eAk = eA, eDk = eD;
        #pragma unroll
        for (int s = 0; s < CH; ++s) {
            float env = (1.0f - eAk) * eDk;
            o[s] = fmaf(nnf[s] * gain_n, env, fmaf(rsf[s], gain_r, tr[s]));
            eAk *= a1; eDk *= d1;
        }
        ((float4*)out)[v0] = make_float4(o[0], o[1], o[2], o[3]);
    }
}

extern "C" void kernel_launch(void* const* d_in, const int* in_sizes, int n_in,
                              void* d_out, int out_size)
{
    const float* params  = (const float*)d_in[0];
    const float* noise_t = (const float*)d_in[1];
    const float* noise_n = (const float*)d_in[2];
    float* out = (float*)d_out;

    cudaFuncSetAttribute(drum_synth_cluster,
                         cudaFuncAttributeMaxDynamicSharedMemorySize,
                         (int)SMEM_BYTES);
    cudaFuncSetAttribute(drum_synth_cluster,
                         cudaFuncAttributeNonPortableClusterSizeAllowed, 1);

    // Preferred: 16-CTA cluster, 512 threads each (same 256-warp lane map).
    cudaLaunchConfig_t cfg = {};
    cfg.gridDim         = dim3(16, 1, 1);
    cfg.blockDim        = dim3(512, 1, 1);
    cfg.dynamicSmemBytes = SMEM_BYTES;
    cfg.stream          = 0;

    int maxc = 0;
    if (cudaOccupancyMaxPotentialClusterSize(&maxc, drum_synth_cluster, &cfg)
        != cudaSuccess) maxc = 8;

    cudaLaunchAttribute attrs[1];
    attrs[0].id = cudaLaunchAttributeClusterDimension;

    if (maxc >= 16) {
        attrs[0].val.clusterDim = {16, 1, 1};
        cfg.attrs = attrs; cfg.numAttrs = 1;
        cudaLaunchKernelEx(&cfg, drum_synth_cluster, params, noise_t, noise_n, out);
    } else {
        // Fallback: proven 8-CTA x 1024-thread configuration (identical lane map).
        cfg.gridDim  = dim3(8, 1, 1);
        cfg.blockDim = dim3(1024, 1, 1);
        attrs[0].val.clusterDim = {8, 1, 1};
        cfg.attrs = attrs; cfg.numAttrs = 1;
        cudaLaunchKernelEx(&cfg, drum_synth_cluster, params, noise_t, noise_n, out);
    }
}

// round 14
// speedup vs baseline: 1.0958x; 1.0735x over previous
#include <cuda_runtime.h>
#include <math.h>

#define NSAMP  24000
#define CH     4             // samples per lane
#define SPW    128           // samples per warp (32 * 4)
#define CUTOFF 0.1f
#define OMC    0.9f          // 1 - CUTOFF
#define LN_A4  (-0.42144206f) // ln(0.9^4)
#define TSTEP  (1.0f / 23999.0f)
#define INV2PI 0.15915494309f
#define BATCH  15
#define SMEM_BYTES (2u * NSAMP * sizeof(float))

// Global scratch (device global: no allocation)
__device__ float g_trans[NSAMP];

__device__ __forceinline__ float tanh_fast(float x) {
    float e = __expf(2.0f * x);
    return 1.0f - __fdividef(2.0f, e + 1.0f);
}

// sincos for args up to ~400 rad: 2-term Cody-Waite reduction + MUFU sin/cos.
__device__ __forceinline__ void sincos_cw(float x, float* s, float* c) {
    float k = rintf(x * INV2PI);
    float r = fmaf(k, -6.28125f, x);
    r = fmaf(k, -1.9353072e-3f, r);
    *s = __sinf(r);
    *c = __cosf(r);
}

// Constant-coefficient inclusive scan (coefficient A4 = 0.9^4, lane-invariant).
__device__ __forceinline__ float scan_const_a4(float b, int lane) {
    const float P[5] = {0.6561f, 0.43046721f, 0.18530202f,
                        0.034336838f, 0.0011790185f};   // A4^{1,2,4,8,16}
    #pragma unroll
    for (int k = 0; k < 5; ++k) {
        int off = 1 << k;
        float bu = __shfl_up_sync(0xffffffffu, b, off);
        if (lane >= off) b = fmaf(P[k], bu, b);
    }
    return b;
}

__device__ __forceinline__ void cluster_sync() {
    asm volatile("barrier.cluster.arrive.aligned;" ::: "memory");
    asm volatile("barrier.cluster.wait.aligned;"   ::: "memory");
}

template <int NT>
__global__ __launch_bounds__(NT, 1)
void drum_synth_cluster(const float* __restrict__ p,
                        const float* __restrict__ noise_t,
                        const float* __restrict__ noise_n,
                        float* __restrict__ out)
{
    extern __shared__ float sm[];      // sre[24000]; str[24000] (generic path only)
    float* sre = sm;
    float* str = sm + NSAMP;

    const int tid  = threadIdx.x;
    const int lane = tid & 31;
    const int w    = blockIdx.x * (NT / 32) + (tid >> 5);   // global warp 0..255

    const int  s0  = w * SPW + lane * CH;
    const bool act = (s0 + CH <= NSAMP);
    const int  v0  = s0 >> 2;
    const float4* ntv = (const float4*)noise_t;

    // ---- earliest possible: prime noise_n into regs (cold DRAM) ----
    float4 nn0 = make_float4(0.f, 0.f, 0.f, 0.f);
    if (act) nn0 = ((const float4*)noise_n)[v0];

    const float decay_t  = p[1];
    const float freq_t   = p[2];
    const float sat      = p[3];
    const float gain_t   = p[4];
    const float freq_r   = p[5];
    const float feedback = p[6];
    const float gain_r   = p[7];
    const float attack_n = p[8];
    const float decay_n  = p[9];
    const float gain_n   = p[10];

    // ======== Phase A1: halo — redundantly reduce previous warp's 128 samples ====
    float hb = 0.0f;
    {
        const int hs0 = s0 - SPW;
        if (hs0 >= 0 && hs0 + CH <= NSAMP) {
            float4 x0 = ntv[hs0 >> 2];
            float y;
            y = CUTOFF * x0.x;
            y = fmaf(OMC, y, CUTOFF * x0.y);
            y = fmaf(OMC, y, CUTOFF * x0.z);
            y = fmaf(OMC, y, CUTOFF * x0.w);
            hb = y;
        }
    }
    hb = scan_const_a4(hb, lane);
    const float y_warp = __shfl_sync(0xffffffffu, hb, 31);

    // ======== Phase A2: main chunk partials from y=0 ========
    float bk[CH];
    float mb = 0.0f;
    if (act) {
        float4 x0 = ntv[v0];
        float xs[CH] = {x0.x, x0.y, x0.z, x0.w};
        float y = 0.0f;
        #pragma unroll
        for (int s = 0; s < CH; ++s) { y = fmaf(OMC, y, CUTOFF * xs[s]); bk[s] = y; }
        mb = y;
    }
    mb = scan_const_a4(mb, lane);
    float b_ie = __shfl_up_sync(0xffffffffu, mb, 1);
    if (lane == 0) b_ie = 0.0f;
    const float a_ie = __expf((float)lane * LN_A4);          // A4^lane
    const float y_in = fmaf(a_ie, y_warp, b_ie);

    // ======== Phase A3: transient via spiral/geometric recurrences ========
    float tr[CH];
    if (act) {
        const float t0 = (float)s0 * TSTEP;
        const float wf = 6.2831853f * freq_t;
        float sn, cs;
        sincos_cw(wf * t0, &sn, &cs);
        const float sd = __sinf(wf * TSTEP);
        const float cd = __cosf(wf * TSTEP);
        const float m1 = __expf(-decay_t * TSTEP);
        const float m2 = __expf(-20.0f * decay_t * TSTEP);
        const float cdm = cd * m1, sdm = sd * m1;
        const float K  = gain_t * sat;
        const float e1 = __expf(-decay_t * t0);
        float u = sn * e1 * K;
        float v = cs * e1 * K;
        float e2g = __expf(-20.0f * decay_t * t0) * (gain_t * 0.5f);
        float q   = OMC * y_in * e2g;
        const float cq = OMC * m2;
        #pragma unroll
        for (int s = 0; s < CH; ++s) {
            float sq = tanh_fast(u);
            tr[s] = sq + fmaf(bk[s], e2g, q);
            float u2 = fmaf(u, cdm,  v * sdm);
            float v2 = fmaf(v, cdm, -u * sdm);
            u = u2; v = v2;
            e2g *= m2; q *= cq;
        }
        ((float4*)g_trans)[v0] = make_float4(tr[0], tr[1], tr[2], tr[3]);
    }

    // cluster barrier: arrive=release orders g_trans stores; wait=acquire.
    cluster_sync();

    // ---- phase-C envelope setup moved here: overlaps chains' L2 waits ----
    const float t0c = (float)s0 * TSTEP;
    float eA = __expf(-attack_n * t0c);
    float eD = __expf(-decay_n  * t0c);
    const float a1 = __expf(-attack_n * TSTEP);
    const float d1 = __expf(-decay_n  * TSTEP);

    // ======== Phase B: resonator, REDUNDANT per CTA ========
    const float D  = 48000.0f / freq_r;
    const int   Di = (int)D;
    const bool fastp = (D >= 1.0f) && ((float)Di == D) && (Di < NSAMP);

    if (fastp) {
        // Integer delay: Di independent chains read g_trans DIRECTLY from L2
        // (lane-coalesced: lanes hold consecutive r). Double-buffered batches
        // of 15 hide L2 latency behind the 15-deep FMA chain of the previous
        // batch. No smem staging, no pre-chain syncthreads.
        for (int r = tid; r < Di; r += NT) {
            float yv = g_trans[r];        // i < D => valid==0 => out = transient
            sre[r] = yv;
            float buf[BATCH];
            int i = r + Di;
            #pragma unroll
            for (int j = 0; j < BATCH; ++j) {
                int idx = i + j * Di;
                buf[j] = (idx < NSAMP) ? g_trans[idx] : 0.0f;
            }
            while (i < NSAMP) {
                const int i2 = i + BATCH * Di;
                float nxt[BATCH];
                #pragma unroll
                for (int j = 0; j < BATCH; ++j) {        // prefetch next batch
                    int idx = i2 + j * Di;
                    nxt[j] = (idx < NSAMP) ? g_trans[idx] : 0.0f;
                }
                #pragma unroll
                for (int j = 0; j < BATCH; ++j) {        // consume current batch
                    int idx = i + j * Di;
                    if (idx < NSAMP) { yv = fmaf(feedback, yv, buf[j]); sre[idx] = yv; }
                }
                #pragma unroll
                for (int j = 0; j < BATCH; ++j) buf[j] = nxt[j];
                i = i2;
            }
        }
        __syncthreads();
    } else {
        // Generic fractional delay: stage into smem, wave-synchronous.
        {
            const float4* tv = (const float4*)g_trans;
            float4*       sv = (float4*)str;
            for (int i4 = tid; i4 < NSAMP / 4; i4 += NT) sv[i4] = tv[i4];
        }
        for (int i = tid; i < NSAMP; i += NT) sre[i] = 0.0f;
        __syncthreads();
        if (tid == 0) sre[0] = str[0];
        int cD = (int)ceilf(D);
        int W  = min(max(cD - 1, 1), NT);
        __syncthreads();
        for (int b0 = 1; b0 < NSAMP; b0 += W) {
            const int i = b0 + tid;
            if (tid < W && i < NSAMP) {
                float delayed = (float)i - D;
                float valid   = (delayed >= 0.0f) ? 1.0f : 0.0f;
                int fl = min(max((int)floorf(delayed), 0), NSAMP - 1);
                int ce = min(fl + 1, NSAMP - 1);
                float frac = delayed - (float)fl;   // after clamp, as in reference
                float interp = (1.0f - frac) * sre[fl] + frac * sre[ce];
                sre[i] = str[i] + feedback * interp * valid;
            }
            __syncthreads();
        }
    }

    // ======== Phase C: noise envelope + final sum (tr in regs, res in smem) ====
    if (act) {
        float4 rs0 = ((const float4*)sre)[v0];
        const float nnf[CH] = {nn0.x, nn0.y, nn0.z, nn0.w};
        const float rsf[CH] = {rs0.x, rs0.y, rs0.z, rs0.w};
        float o[CH];
        float eAk = eA, eDk = eD;
        #pragma unroll
        for (int s = 0; s < CH; ++s) {
            float env = (1.0f - eAk) * eDk;
            o[s] = fmaf(nnf[s] * gain_n, env, fmaf(rsf[s], gain_r, tr[s]));
            eAk *= a1; eDk *= d1;
        }
        ((float4*)out)[v0] = make_float4(o[0], o[1], o[2], o[3]);
    }
}

extern "C" void kernel_launch(void* const* d_in, const int* in_sizes, int n_in,
                              void* d_out, int out_size)
{
    const float* params  = (const float*)d_in[0];
    const float* noise_t = (const float*)d_in[1];
    const float* noise_n = (const float*)d_in[2];
    float* out = (float*)d_out;

    cudaFuncSetAttribute(drum_synth_cluster<512>,
                         cudaFuncAttributeMaxDynamicSharedMemorySize, (int)SMEM_BYTES);
    cudaFuncSetAttribute(drum_synth_cluster<512>,
                         cudaFuncAttributeNonPortableClusterSizeAllowed, 1);

    // Preferred: 16-CTA cluster, 512 threads each (256-warp lane map).
    cudaLaunchConfig_t cfg = {};
    cfg.gridDim          = dim3(16, 1, 1);
    cfg.blockDim         = dim3(512, 1, 1);
    cfg.dynamicSmemBytes = SMEM_BYTES;
    cfg.stream           = 0;

    int maxc = 0;
    if (cudaOccupancyMaxPotentialClusterSize(&maxc, drum_synth_cluster<512>, &cfg)
        != cudaSuccess) maxc = 8;

    cudaLaunchAttribute attrs[1];
    attrs[0].id = cudaLaunchAttributeClusterDimension;

    if (maxc >= 16) {
        attrs[0].val.clusterDim = {16, 1, 1};
        cfg.attrs = attrs; cfg.numAttrs = 1;
        cudaLaunchKernelEx(&cfg, drum_synth_cluster<512>, params, noise_t, noise_n, out);
    } else {
        // Fallback: 8-CTA x 1024-thread configuration (identical lane map).
        cudaFuncSetAttribute(drum_synth_cluster<1024>,
                             cudaFuncAttributeMaxDynamicSharedMemorySize, (int)SMEM_BYTES);
        cfg.gridDim  = dim3(8, 1, 1);
        cfg.blockDim = dim3(1024, 1, 1);
        attrs[0].val.clusterDim = {8, 1, 1};
        cfg.attrs = attrs; cfg.numAttrs = 1;
        cudaLaunchKernelEx(&cfg, drum_synth_cluster<1024>, params, noise_t, noise_n, out);
    }
}

// round 15
// speedup vs baseline: 1.2294x; 1.1219x over previous
#include <cuda_runtime.h>
#include <math.h>

#define NSAMP  24000
#define CH     4             // samples per lane
#define SPW    128           // samples per warp (32 * 4)
#define CUTOFF 0.1f
#define OMC    0.9f          // 1 - CUTOFF
#define LN_A4  (-0.42144206f) // ln(0.9^4)
#define TSTEP  (1.0f / 23999.0f)
#define INV2PI 0.15915494309f
#define BATCH  15
#define SMEM_BYTES (2u * NSAMP * sizeof(float))

// Global scratch (device global: no allocation)
__device__ float g_trans[NSAMP];

__device__ __forceinline__ float tanh_fast(float x) {
    float e = __expf(2.0f * x);
    return 1.0f - __fdividef(2.0f, e + 1.0f);
}

// sincos for args up to ~400 rad: 2-term Cody-Waite reduction + MUFU sin/cos.
__device__ __forceinline__ void sincos_cw(float x, float* s, float* c) {
    float k = rintf(x * INV2PI);
    float r = fmaf(k, -6.28125f, x);
    r = fmaf(k, -1.9353072e-3f, r);
    *s = __sinf(r);
    *c = __cosf(r);
}

// Constant-coefficient inclusive scan (coefficient A4 = 0.9^4, lane-invariant).
__device__ __forceinline__ float scan_const_a4(float b, int lane) {
    const float P[5] = {0.6561f, 0.43046721f, 0.18530202f,
                        0.034336838f, 0.0011790185f};   // A4^{1,2,4,8,16}
    #pragma unroll
    for (int k = 0; k < 5; ++k) {
        int off = 1 << k;
        float bu = __shfl_up_sync(0xffffffffu, b, off);
        if (lane >= off) b = fmaf(P[k], bu, b);
    }
    return b;
}

__device__ __forceinline__ void cluster_sync() {
    asm volatile("barrier.cluster.arrive.aligned;" ::: "memory");
    asm volatile("barrier.cluster.wait.aligned;"   ::: "memory");
}

template <int NT>
__global__ __launch_bounds__(NT, 1)
void drum_synth_cluster(const float* __restrict__ p,
                        const float* __restrict__ noise_t,
                        const float* __restrict__ noise_n,
                        float* __restrict__ out)
{
    extern __shared__ float sm[];      // sre[24000]; str[24000] (generic path only)
    float* sre = sm;
    float* str = sm + NSAMP;

    const int tid  = threadIdx.x;
    const int lane = tid & 31;
    const int w    = blockIdx.x * (NT / 32) + (tid >> 5);   // global warp 0..255

    const int  s0  = w * SPW + lane * CH;
    const bool act = (s0 + CH <= NSAMP);
    const int  v0  = s0 >> 2;
    const float4* ntv = (const float4*)noise_t;

    // ---- earliest possible: prime noise_n into regs (cold DRAM) ----
    float4 nn0 = make_float4(0.f, 0.f, 0.f, 0.f);
    if (act) nn0 = ((const float4*)noise_n)[v0];

    const float decay_t  = p[1];
    const float freq_t   = p[2];
    const float sat      = p[3];
    const float gain_t   = p[4];
    const float freq_r   = p[5];
    const float feedback = p[6];
    const float gain_r   = p[7];
    const float attack_n = p[8];
    const float decay_n  = p[9];
    const float gain_n   = p[10];

    // ======== Phase A1: halo — redundantly reduce previous warp's 128 samples ====
    float hb = 0.0f;
    {
        const int hs0 = s0 - SPW;
        if (hs0 >= 0 && hs0 + CH <= NSAMP) {
            float4 x0 = ntv[hs0 >> 2];
            float y;
            y = CUTOFF * x0.x;
            y = fmaf(OMC, y, CUTOFF * x0.y);
            y = fmaf(OMC, y, CUTOFF * x0.z);
            y = fmaf(OMC, y, CUTOFF * x0.w);
            hb = y;
        }
    }
    hb = scan_const_a4(hb, lane);
    const float y_warp = __shfl_sync(0xffffffffu, hb, 31);

    // ======== Phase A2: main chunk partials from y=0 ========
    float bk[CH];
    float mb = 0.0f;
    if (act) {
        float4 x0 = ntv[v0];
        float xs[CH] = {x0.x, x0.y, x0.z, x0.w};
        float y = 0.0f;
        #pragma unroll
        for (int s = 0; s < CH; ++s) { y = fmaf(OMC, y, CUTOFF * xs[s]); bk[s] = y; }
        mb = y;
    }
    mb = scan_const_a4(mb, lane);
    float b_ie = __shfl_up_sync(0xffffffffu, mb, 1);
    if (lane == 0) b_ie = 0.0f;
    const float a_ie = __expf((float)lane * LN_A4);          // A4^lane
    const float y_in = fmaf(a_ie, y_warp, b_ie);

    // ======== Phase A3: transient via spiral/geometric recurrences ========
    float tr[CH];
    if (act) {
        const float t0 = (float)s0 * TSTEP;
        const float wf = 6.2831853f * freq_t;
        float sn, cs;
        sincos_cw(wf * t0, &sn, &cs);
        const float sd = __sinf(wf * TSTEP);
        const float cd = __cosf(wf * TSTEP);
        const float m1 = __expf(-decay_t * TSTEP);
        const float m2 = __expf(-20.0f * decay_t * TSTEP);
        const float cdm = cd * m1, sdm = sd * m1;
        const float K  = gain_t * sat;
        const float e1 = __expf(-decay_t * t0);
        float u = sn * e1 * K;
        float v = cs * e1 * K;
        float e2g = __expf(-20.0f * decay_t * t0) * (gain_t * 0.5f);
        float q   = OMC * y_in * e2g;
        const float cq = OMC * m2;
        #pragma unroll
        for (int s = 0; s < CH; ++s) {
            float sq = tanh_fast(u);
            tr[s] = sq + fmaf(bk[s], e2g, q);
            float u2 = fmaf(u, cdm,  v * sdm);
            float v2 = fmaf(v, cdm, -u * sdm);
            u = u2; v = v2;
            e2g *= m2; q *= cq;
        }
        ((float4*)g_trans)[v0] = make_float4(tr[0], tr[1], tr[2], tr[3]);
    }

    // cluster barrier: arrive=release orders g_trans stores; wait=acquire.
    cluster_sync();

    // ---- phase-C envelope setup here: overlaps chains' L2 waits ----
    const float t0c = (float)s0 * TSTEP;
    float eA = __expf(-attack_n * t0c);
    float eD = __expf(-decay_n  * t0c);
    const float a1 = __expf(-attack_n * TSTEP);
    const float d1 = __expf(-decay_n  * TSTEP);

    // ======== Phase B: resonator, REDUNDANT per CTA ========
    const float D  = 48000.0f / freq_r;
    const int   Di = (int)D;
    const bool fastp = (D >= 1.0f) && ((float)Di == D) && (Di < NSAMP);

    if (fastp) {
        // Integer delay: Di independent chains read g_trans directly from L2
        // (lane-coalesced). Full batches are PREDICATE-FREE (load 15, then
        // 15 FMA+STS); one final predicated batch handles the remainder with
        // MLP=BATCH so no serial L2 latency is exposed.
        for (int r = tid; r < Di; r += NT) {
            float yv = g_trans[r];        // i < D => valid==0 => out = transient
            sre[r] = yv;
            int i = r + Di;
            // full batches: all BATCH elements in range, no predicates
            while (i + (BATCH - 1) * Di < NSAMP) {
                float buf[BATCH];
                #pragma unroll
                for (int j = 0; j < BATCH; ++j) buf[j] = g_trans[i + j * Di];
                #pragma unroll
                for (int j = 0; j < BATCH; ++j) {
                    yv = fmaf(feedback, yv, buf[j]);
                    sre[i + j * Di] = yv;
                }
                i += BATCH * Di;
            }
            // final partial batch (predicated, loads still issued in parallel)
            if (i < NSAMP) {
                float buf[BATCH];
                #pragma unroll
                for (int j = 0; j < BATCH; ++j) {
                    int idx = i + j * Di;
                    buf[j] = (idx < NSAMP) ? g_trans[idx] : 0.0f;
                }
                #pragma unroll
                for (int j = 0; j < BATCH; ++j) {
                    int idx = i + j * Di;
                    if (idx < NSAMP) { yv = fmaf(feedback, yv, buf[j]); sre[idx] = yv; }
                }
            }
        }
        __syncthreads();
    } else {
        // Generic fractional delay: stage into smem, wave-synchronous.
        {
            const float4* tv = (const float4*)g_trans;
            float4*       sv = (float4*)str;
            for (int i4 = tid; i4 < NSAMP / 4; i4 += NT) sv[i4] = tv[i4];
        }
        for (int i = tid; i < NSAMP; i += NT) sre[i] = 0.0f;
        __syncthreads();
        if (tid == 0) sre[0] = str[0];
        int cD = (int)ceilf(D);
        int W  = min(max(cD - 1, 1), NT);
        __syncthreads();
        for (int b0 = 1; b0 < NSAMP; b0 += W) {
            const int i = b0 + tid;
            if (tid < W && i < NSAMP) {
                float delayed = (float)i - D;
                float valid   = (delayed >= 0.0f) ? 1.0f : 0.0f;
                int fl = min(max((int)floorf(delayed), 0), NSAMP - 1);
                int ce = min(fl + 1, NSAMP - 1);
                float frac = delayed - (float)fl;   // after clamp, as in reference
                float interp = (1.0f - frac) * sre[fl] + frac * sre[ce];
                sre[i] = str[i] + feedback * interp * valid;
            }
            __syncthreads();
        }
    }

    // ======== Phase C: noise envelope + final sum (tr in regs, res in smem) ====
    if (act) {
        float4 rs0 = ((const float4*)sre)[v0];
        const float nnf[CH] = {nn0.x, nn0.y, nn0.z, nn0.w};
        const float rsf[CH] = {rs0.x, rs0.y, rs0.z, rs0.w};
        float o[CH];
        float eAk = eA, eDk = eD;
        #pragma unroll
        for (int s = 0; s < CH; ++s) {
            float env = (1.0f - eAk) * eDk;
            o[s] = fmaf(nnf[s] * gain_n, env, fmaf(rsf[s], gain_r, tr[s]));
            eAk *= a1; eDk *= d1;
        }
        ((float4*)out)[v0] = make_float4(o[0], o[1], o[2], o[3]);
    }
}

extern "C" void kernel_launch(void* const* d_in, const int* in_sizes, int n_in,
                              void* d_out, int out_size)
{
    const float* params  = (const float*)d_in[0];
    const float* noise_t = (const float*)d_in[1];
    const float* noise_n = (const float*)d_in[2];
    float* out = (float*)d_out;

    cudaFuncSetAttribute(drum_synth_cluster<512>,
                         cudaFuncAttributeMaxDynamicSharedMemorySize, (int)SMEM_BYTES);
    cudaFuncSetAttribute(drum_synth_cluster<512>,
                         cudaFuncAttributeNonPortableClusterSizeAllowed, 1);

    // Preferred: 16-CTA cluster, 512 threads each (256-warp lane map).
    cudaLaunchConfig_t cfg = {};
    cfg.gridDim          = dim3(16, 1, 1);
    cfg.blockDim         = dim3(512, 1, 1);
    cfg.dynamicSmemBytes = SMEM_BYTES;
    cfg.stream           = 0;

    int maxc = 0;
    if (cudaOccupancyMaxPotentialClusterSize(&maxc, drum_synth_cluster<512>, &cfg)
        != cudaSuccess) maxc = 8;

    cudaLaunchAttribute attrs[1];
    attrs[0].id = cudaLaunchAttributeClusterDimension;

    if (maxc >= 16) {
        attrs[0].val.clusterDim = {16, 1, 1};
        cfg.attrs = attrs; cfg.numAttrs = 1;
        cudaLaunchKernelEx(&cfg, drum_synth_cluster<512>, params, noise_t, noise_n, out);
    } else {
        // Fallback: 8-CTA x 1024-thread configuration (identical lane map).
        cudaFuncSetAttribute(drum_synth_cluster<1024>,
                             cudaFuncAttributeMaxDynamicSharedMemorySize, (int)SMEM_BYTES);
        cfg.gridDim  = dim3(8, 1, 1);
        cfg.blockDim = dim3(1024, 1, 1);
        attrs[0].val.clusterDim = {8, 1, 1};
        cfg.attrs = attrs; cfg.numAttrs = 1;
        cudaLaunchKernelEx(&cfg, drum_synth_cluster<1024>, params, noise_t, noise_n, out);
    }
}